// round 12
// baseline (speedup 1.0000x reference)
#include <cuda_runtime.h>
#include <cstdint>

#define NE 64
#define KD 2048
#define TM 128
#define KC 32                    // fp32 k-elements per chunk
#define NCHUNK (KD / KC)         // 64
#define NTHREADS 256
#define STRIDE 80                // smem row stride (bytes): gcd(5,8)=1 -> conflict-free ldmatrix

#define XSPLIT (TM * STRIDE)     // 10240 bytes: one X split plane
#define WOFF   (6 * XSPLIT)      // X double-buffer (2 bufs x 3 planes) = 61440
#define WSPLIT (NE * STRIDE)     // 5120 bytes: one W split plane
#define DYN_SMEM (WOFF + 6 * WSPLIT)   // 92160
// epilogue overlay: Sc[128][65] f32 + Fi[128][8] f32 = 37376 <= 92160

// pre-split W in final smem byte layout: [chunk][plane][64 rows x 80B]
__device__ __align__(16) unsigned char Wsc[NCHUNK][3][WSPLIT];

// ---------------- PTX helpers (base ISA only) ----------------
#define CPASYNC16(s, g) asm volatile("cp.async.cg.shared.global [%0], [%1], 16;" :: "r"(s), "l"(g))
#define CPCOMMIT()      asm volatile("cp.async.commit_group;")
#define CPWAIT(n)       asm volatile("cp.async.wait_group %0;" :: "n"(n))

#define LDSM4(r, addr) \
    asm volatile("ldmatrix.sync.aligned.m8n8.x4.shared.b16 {%0,%1,%2,%3}, [%4];" \
        : "=r"((r)[0]), "=r"((r)[1]), "=r"((r)[2]), "=r"((r)[3]) : "r"(addr))

#define MMA16816(d, a, b0, b1) \
    asm volatile("mma.sync.aligned.m16n8k16.row.col.f32.bf16.bf16.f32 " \
        "{%0,%1,%2,%3},{%4,%5,%6,%7},{%8,%9},{%0,%1,%2,%3};" \
        : "+f"((d)[0]), "+f"((d)[1]), "+f"((d)[2]), "+f"((d)[3]) \
        : "r"((a)[0]), "r"((a)[1]), "r"((a)[2]), "r"((a)[3]), "r"(b0), "r"(b1))

// exact 3-term split of an fp32 pair into bf16x2 planes (x = p0+p1+p2 to ~2^-33)
__device__ __forceinline__ void split3(float a, float b,
                                       uint32_t& p0, uint32_t& p1, uint32_t& p2)
{
    asm("cvt.rn.bf16x2.f32 %0, %1, %2;" : "=r"(p0) : "f"(b), "f"(a));
    float a1 = a - __uint_as_float(p0 << 16);
    float b1 = b - __uint_as_float(p0 & 0xffff0000u);
    asm("cvt.rn.bf16x2.f32 %0, %1, %2;" : "=r"(p1) : "f"(b1), "f"(a1));
    float a2 = a1 - __uint_as_float(p1 << 16);
    float b2 = b1 - __uint_as_float(p1 & 0xffff0000u);
    asm("cvt.rn.bf16x2.f32 %0, %1, %2;" : "=r"(p2) : "f"(b2), "f"(a2));
}

// ---------------- W pre-split kernel ----------------
__global__ void wconv_kernel(const float* __restrict__ W)
{
    int i = blockIdx.x * blockDim.x + threadIdx.x;  // 16384 threads, 8 f32 each
    int gi = i * 8;
    int e = gi >> 11;
    int k0 = gi & 2047;
    const float4* p = reinterpret_cast<const float4*>(W + (size_t)e * KD + k0);
    float4 v0 = p[0], v1 = p[1];
    uint4 u0, u1, u2;
    split3(v0.x, v0.y, u0.x, u1.x, u2.x);
    split3(v0.z, v0.w, u0.y, u1.y, u2.y);
    split3(v1.x, v1.y, u0.z, u1.z, u2.z);
    split3(v1.z, v1.w, u0.w, u1.w, u2.w);
    int c = k0 >> 5;
    uint32_t off = (uint32_t)(e * STRIDE + ((k0 & 31) >> 3) * 16);
    *reinterpret_cast<uint4*>(&Wsc[c][0][off]) = u0;
    *reinterpret_cast<uint4*>(&Wsc[c][1][off]) = u1;
    *reinterpret_cast<uint4*>(&Wsc[c][2][off]) = u2;
}

// ---------------- main kernel ----------------
extern __shared__ __align__(16) unsigned char dsm[];

__device__ __forceinline__ void stage_w(uint32_t Bs, int t, int buf, int tid)
{
    #pragma unroll
    for (int r = 0; r < 3; ++r) {
        int idx = tid + r * 256;          // 768 x 16B data chunks (3 planes x 64 rows x 4)
        int s = idx >> 8;                 // plane
        int row = (idx >> 2) & 63;
        int c = idx & 3;
        uint32_t off = (uint32_t)(row * STRIDE + c * 16);
        uint32_t dst = Bs + WOFF + (uint32_t)((3 * buf + s) * WSPLIT) + off;
        CPASYNC16(dst, &Wsc[t][s][0] + off);
    }
}

__global__ void __launch_bounds__(NTHREADS, 2)
router_mma(const float* __restrict__ X,
           const float* __restrict__ Bv,
           float* __restrict__ out, int ntok)
{
    __shared__ float s_bias[NE];

    const int tid = threadIdx.x;
    const int lane = tid & 31;
    const int wid = tid >> 5;
    const int wm = wid >> 1;           // token group (0..3) -> 32 tokens
    const int wn = wid & 1;            // expert group (0..1) -> 32 experts
    const int tokbase = blockIdx.x * TM;

    const uint32_t Bs = (uint32_t)__cvta_generic_to_shared(dsm);

    if (tid < NE) s_bias[tid] = Bv[tid];

    // prologue: stage W chunks 0,1
    stage_w(Bs, 0, 0, tid);
    CPCOMMIT();
    stage_w(Bs, 1, 1, tid);
    CPCOMMIT();

    // X staging mapping: thread -> (token, half-row of 16 f32)
    const int tok = tid >> 1, h = tid & 1;
    const float* Xrow = X + (size_t)(tokbase + tok) * KD + h * 16;
    const uint32_t xst = (uint32_t)(tok * STRIDE + h * 32);   // byte offset of this thread's 32B

    // ldmatrix lane offsets
    const uint32_t a_row  = (uint32_t)(wm * 32 + (lane & 7) + ((lane >> 3) & 1) * 8);
    const uint32_t a_csel = (uint32_t)(lane >> 4);
    const uint32_t aoff0 = a_row * STRIDE + a_csel * 16;
    const uint32_t aoff1 = (a_row + 16) * STRIDE + a_csel * 16;
    const uint32_t b_row  = (uint32_t)(wn * 32 + (lane & 7) + (lane >> 4) * 8);
    const uint32_t b_csel = (uint32_t)((lane >> 3) & 1);
    const uint32_t boff0 = b_row * STRIDE + b_csel * 16;
    const uint32_t boff1 = (b_row + 16) * STRIDE + b_csel * 16;

    // running sums (proper RN fp32 adds between chunks)
    float sum[2][4][4];
    #pragma unroll
    for (int i = 0; i < 2; ++i)
        #pragma unroll
        for (int j = 0; j < 4; ++j)
            #pragma unroll
            for (int r = 0; r < 4; ++r) sum[i][j][r] = 0.0f;

    float4 xv[4];
    {
        const float4* p = reinterpret_cast<const float4*>(Xrow);
        xv[0] = p[0]; xv[1] = p[1]; xv[2] = p[2]; xv[3] = p[3];
    }

    for (int t = 0; t < NCHUNK; ++t) {
        const int b = t & 1;

        // exact-split-store X(t) into the 3 planes of buffer b
        {
            uint4 u0[2], u1[2], u2[2];
            split3(xv[0].x, xv[0].y, u0[0].x, u1[0].x, u2[0].x);
            split3(xv[0].z, xv[0].w, u0[0].y, u1[0].y, u2[0].y);
            split3(xv[1].x, xv[1].y, u0[0].z, u1[0].z, u2[0].z);
            split3(xv[1].z, xv[1].w, u0[0].w, u1[0].w, u2[0].w);
            split3(xv[2].x, xv[2].y, u0[1].x, u1[1].x, u2[1].x);
            split3(xv[2].z, xv[2].w, u0[1].y, u1[1].y, u2[1].y);
            split3(xv[3].x, xv[3].y, u0[1].z, u1[1].z, u2[1].z);
            split3(xv[3].z, xv[3].w, u0[1].w, u1[1].w, u2[1].w);
            unsigned char* x0 = dsm + (3 * b + 0) * XSPLIT + xst;
            unsigned char* x1 = dsm + (3 * b + 1) * XSPLIT + xst;
            unsigned char* x2 = dsm + (3 * b + 2) * XSPLIT + xst;
            *reinterpret_cast<uint4*>(x0)      = u0[0];
            *reinterpret_cast<uint4*>(x0 + 16) = u0[1];
            *reinterpret_cast<uint4*>(x1)      = u1[0];
            *reinterpret_cast<uint4*>(x1 + 16) = u1[1];
            *reinterpret_cast<uint4*>(x2)      = u2[0];
            *reinterpret_cast<uint4*>(x2 + 16) = u2[1];
        }

        // prefetch X(t+1) into xv (xv dead after split-store; LDG in flight across wait+mma)
        if (t + 1 < NCHUNK) {
            const float4* p = reinterpret_cast<const float4*>(Xrow + (t + 1) * KC);
            xv[0] = p[0]; xv[1] = p[1]; xv[2] = p[2]; xv[3] = p[3];
        }

        if (t == NCHUNK - 1) { CPWAIT(0); } else { CPWAIT(1); }
        __syncthreads();

        // fresh accumulators per chunk (bounds tensor-core RZ accumulation bias)
        float acc[2][4][4];
        #pragma unroll
        for (int i = 0; i < 2; ++i)
            #pragma unroll
            for (int j = 0; j < 4; ++j)
                #pragma unroll
                for (int r = 0; r < 4; ++r) acc[i][j][r] = 0.0f;

        // consume buffer b
        const uint32_t xs = Bs + (uint32_t)(3 * b) * XSPLIT;
        const uint32_t ws = Bs + WOFF + (uint32_t)(3 * b) * WSPLIT;
        #pragma unroll
        for (int ks = 0; ks < 2; ++ks) {
            const uint32_t ko = (uint32_t)(ks * 32);
            uint32_t a[3][2][4], bx[3][8];
            #pragma unroll
            for (int s = 0; s < 3; ++s) {
                LDSM4(a[s][0], xs + s * XSPLIT + aoff0 + ko);
                LDSM4(a[s][1], xs + s * XSPLIT + aoff1 + ko);
                LDSM4(bx[s],     ws + s * WSPLIT + boff0 + ko);
                LDSM4(bx[s] + 4, ws + s * WSPLIT + boff1 + ko);
            }
            // products: (0,0) (0,1) (1,0) (1,1) (0,2) (2,0)
            #pragma unroll
            for (int nt = 0; nt < 4; ++nt) {
                MMA16816(acc[0][nt], a[0][0], bx[0][2 * nt], bx[0][2 * nt + 1]);
                MMA16816(acc[1][nt], a[0][1], bx[0][2 * nt], bx[0][2 * nt + 1]);
                MMA16816(acc[0][nt], a[0][0], bx[1][2 * nt], bx[1][2 * nt + 1]);
                MMA16816(acc[1][nt], a[0][1], bx[1][2 * nt], bx[1][2 * nt + 1]);
                MMA16816(acc[0][nt], a[1][0], bx[0][2 * nt], bx[0][2 * nt + 1]);
                MMA16816(acc[1][nt], a[1][1], bx[0][2 * nt], bx[0][2 * nt + 1]);
                MMA16816(acc[0][nt], a[1][0], bx[1][2 * nt], bx[1][2 * nt + 1]);
                MMA16816(acc[1][nt], a[1][1], bx[1][2 * nt], bx[1][2 * nt + 1]);
                MMA16816(acc[0][nt], a[0][0], bx[2][2 * nt], bx[2][2 * nt + 1]);
                MMA16816(acc[1][nt], a[0][1], bx[2][2 * nt], bx[2][2 * nt + 1]);
                MMA16816(acc[0][nt], a[2][0], bx[0][2 * nt], bx[0][2 * nt + 1]);
                MMA16816(acc[1][nt], a[2][1], bx[0][2 * nt], bx[0][2 * nt + 1]);
            }
        }

        // fold chunk result into running sum with RN adds
        #pragma unroll
        for (int i = 0; i < 2; ++i)
            #pragma unroll
            for (int j = 0; j < 4; ++j)
                #pragma unroll
                for (int r = 0; r < 4; ++r) sum[i][j][r] += acc[i][j][r];

        __syncthreads();

        // refill W buffer b with chunk t+2
        if (t + 2 < NCHUNK) {
            stage_w(Bs, t + 2, b, tid);
            CPCOMMIT();
        }
    }

    // ================= epilogue =================
    float (*Sc)[65] = reinterpret_cast<float(*)[65]>(dsm);
    float (*Fi)[8]  = reinterpret_cast<float(*)[8]>(dsm + TM * 65 * 4);

    #pragma unroll
    for (int mt = 0; mt < 2; ++mt)
        #pragma unroll
        for (int nt = 0; nt < 4; ++nt)
            #pragma unroll
            for (int r = 0; r < 4; ++r) {
                int row = wm * 32 + mt * 16 + (lane >> 2) + (r >> 1) * 8;
                int col = wn * 32 + nt * 8 + (lane & 3) * 2 + (r & 1);
                Sc[row][col] = sum[mt][nt][r] + s_bias[col];
            }
    __syncthreads();

    if (tid < TM) {
        unsigned long long taken = 0ULL;
        float vals[8];
        int idxs[8];
        #pragma unroll
        for (int k = 0; k < 8; ++k) {
            float bv = -3.4e38f;
            int bi = 0;
            for (int e = 0; e < NE; ++e) {
                float se = Sc[tid][e];
                bool avail = !((taken >> e) & 1ULL);
                if (avail && se > bv) { bv = se; bi = e; }
            }
            vals[k] = bv;
            idxs[k] = bi;
            taken |= 1ULL << bi;
        }
        float mx = fmaxf(vals[0], 0.0f);
        float denom = (float)(NE - 8) * __expf(-mx);
        #pragma unroll
        for (int k = 0; k < 8; ++k) denom += __expf(vals[k] - mx);
        float inv = 1.0f / denom;
        float z = __expf(-mx) * inv;
        for (int e = 0; e < NE; ++e) Sc[tid][e] = z;
        #pragma unroll
        for (int k = 0; k < 8; ++k) Sc[tid][idxs[k]] = __expf(vals[k] - mx) * inv;
        #pragma unroll
        for (int k = 0; k < 8; ++k) Fi[tid][k] = (float)idxs[k];
    }
    __syncthreads();

    float* ro = out + (size_t)tokbase * NE;
    for (int i = tid; i < TM * NE; i += NTHREADS) ro[i] = Sc[i >> 6][i & 63];
    float* io = out + (size_t)ntok * NE + (size_t)tokbase * 8;
    for (int i = tid; i < TM * 8; i += NTHREADS) io[i] = Fi[i >> 3][i & 7];
}

extern "C" void kernel_launch(void* const* d_in, const int* in_sizes, int n_in,
                              void* d_out, int out_size)
{
    const float* X = nullptr;
    const float* Wm = nullptr;
    const float* Bv = nullptr;
    int nx = 0;
    for (int i = 0; i < n_in; ++i) {
        if (in_sizes[i] == NE) Bv = (const float*)d_in[i];
        else if (in_sizes[i] == NE * KD) Wm = (const float*)d_in[i];
        else { X = (const float*)d_in[i]; nx = in_sizes[i]; }
    }
    int ntok = nx / KD;                 // 32768
    int grid = ntok / TM;               // 256

    cudaFuncSetAttribute(router_mma, cudaFuncAttributeMaxDynamicSharedMemorySize, DYN_SMEM);

    wconv_kernel<<<64, 256>>>(Wm);
    router_mma<<<grid, NTHREADS, DYN_SMEM>>>(X, Bv, (float*)d_out, ntok);
}

// round 13
// speedup vs baseline: 1.0002x; 1.0002x over previous
#include <cuda_runtime.h>
#include <cstdint>

#define NE 64
#define KD 2048
#define TM 128
#define KC 32                    // fp32 k-elements per chunk
#define NCHUNK (KD / KC)         // 64
#define NTHREADS 256
#define STRIDE 80                // smem row stride (bytes): gcd(5,8)=1 -> conflict-free ldmatrix

#define XSPLIT (TM * STRIDE)     // 10240 bytes: one X split plane
#define WOFF   (6 * XSPLIT)      // X double-buffer (2 bufs x 3 planes) = 61440
#define WSPLIT (NE * STRIDE)     // 5120 bytes: one W split plane
#define DYN_SMEM (WOFF + 6 * WSPLIT)   // 92160
// epilogue overlay: Sc[128][65] f32 + Fi[128][8] f32 = 37376 <= 92160

// pre-split W in final smem byte layout: [chunk][plane][64 rows x 80B]
__device__ __align__(16) unsigned char Wsc[NCHUNK][3][WSPLIT];

// ---------------- PTX helpers (base ISA only) ----------------
#define CPASYNC16(s, g) asm volatile("cp.async.cg.shared.global [%0], [%1], 16;" :: "r"(s), "l"(g))
#define CPCOMMIT()      asm volatile("cp.async.commit_group;")
#define CPWAIT(n)       asm volatile("cp.async.wait_group %0;" :: "n"(n))

#define LDSM4(r, addr) \
    asm volatile("ldmatrix.sync.aligned.m8n8.x4.shared.b16 {%0,%1,%2,%3}, [%4];" \
        : "=r"((r)[0]), "=r"((r)[1]), "=r"((r)[2]), "=r"((r)[3]) : "r"(addr))

#define MMA16816(d, a, b0, b1) \
    asm volatile("mma.sync.aligned.m16n8k16.row.col.f32.bf16.bf16.f32 " \
        "{%0,%1,%2,%3},{%4,%5,%6,%7},{%8,%9},{%0,%1,%2,%3};" \
        : "+f"((d)[0]), "+f"((d)[1]), "+f"((d)[2]), "+f"((d)[3]) \
        : "r"((a)[0]), "r"((a)[1]), "r"((a)[2]), "r"((a)[3]), "r"(b0), "r"(b1))

// exact 3-term split of an fp32 pair into bf16x2 planes (x = p0+p1+p2 to ~2^-33)
__device__ __forceinline__ void split3(float a, float b,
                                       uint32_t& p0, uint32_t& p1, uint32_t& p2)
{
    asm("cvt.rn.bf16x2.f32 %0, %1, %2;" : "=r"(p0) : "f"(b), "f"(a));
    float a1 = a - __uint_as_float(p0 << 16);
    float b1 = b - __uint_as_float(p0 & 0xffff0000u);
    asm("cvt.rn.bf16x2.f32 %0, %1, %2;" : "=r"(p1) : "f"(b1), "f"(a1));
    float a2 = a1 - __uint_as_float(p1 << 16);
    float b2 = b1 - __uint_as_float(p1 & 0xffff0000u);
    asm("cvt.rn.bf16x2.f32 %0, %1, %2;" : "=r"(p2) : "f"(b2), "f"(a2));
}

// ---------------- W pre-split kernel ----------------
__global__ void wconv_kernel(const float* __restrict__ W)
{
    int i = blockIdx.x * blockDim.x + threadIdx.x;  // 16384 threads, 8 f32 each
    int gi = i * 8;
    int e = gi >> 11;
    int k0 = gi & 2047;
    const float4* p = reinterpret_cast<const float4*>(W + (size_t)e * KD + k0);
    float4 v0 = p[0], v1 = p[1];
    uint4 u0, u1, u2;
    split3(v0.x, v0.y, u0.x, u1.x, u2.x);
    split3(v0.z, v0.w, u0.y, u1.y, u2.y);
    split3(v1.x, v1.y, u0.z, u1.z, u2.z);
    split3(v1.z, v1.w, u0.w, u1.w, u2.w);
    int c = k0 >> 5;
    uint32_t off = (uint32_t)(e * STRIDE + ((k0 & 31) >> 3) * 16);
    *reinterpret_cast<uint4*>(&Wsc[c][0][off]) = u0;
    *reinterpret_cast<uint4*>(&Wsc[c][1][off]) = u1;
    *reinterpret_cast<uint4*>(&Wsc[c][2][off]) = u2;
}

// ---------------- main kernel ----------------
extern __shared__ __align__(16) unsigned char dsm[];

__device__ __forceinline__ void stage_w(uint32_t Bs, int t, int buf, int tid)
{
    #pragma unroll
    for (int r = 0; r < 3; ++r) {
        int idx = tid + r * 256;          // 768 x 16B data chunks (3 planes x 64 rows x 4)
        int s = idx >> 8;                 // plane
        int row = (idx >> 2) & 63;
        int c = idx & 3;
        uint32_t off = (uint32_t)(row * STRIDE + c * 16);
        uint32_t dst = Bs + WOFF + (uint32_t)((3 * buf + s) * WSPLIT) + off;
        CPASYNC16(dst, &Wsc[t][s][0] + off);
    }
}

__global__ void __launch_bounds__(NTHREADS, 2)
router_mma(const float* __restrict__ X,
           const float* __restrict__ Bv,
           float* __restrict__ out, int ntok)
{
    __shared__ float s_bias[NE];

    const int tid = threadIdx.x;
    const int lane = tid & 31;
    const int wid = tid >> 5;
    const int wm = wid >> 1;           // token group (0..3) -> 32 tokens
    const int wn = wid & 1;            // expert group (0..1) -> 32 experts
    const int tokbase = blockIdx.x * TM;

    const uint32_t Bs = (uint32_t)__cvta_generic_to_shared(dsm);

    if (tid < NE) s_bias[tid] = Bv[tid];

    // prologue: stage W chunks 0,1
    stage_w(Bs, 0, 0, tid);
    CPCOMMIT();
    stage_w(Bs, 1, 1, tid);
    CPCOMMIT();

    // X staging mapping: thread -> (token, half-row of 16 f32)
    const int tok = tid >> 1, h = tid & 1;
    const float* Xrow = X + (size_t)(tokbase + tok) * KD + h * 16;
    const uint32_t xst = (uint32_t)(tok * STRIDE + h * 32);   // byte offset of this thread's 32B

    // ldmatrix lane offsets
    const uint32_t a_row  = (uint32_t)(wm * 32 + (lane & 7) + ((lane >> 3) & 1) * 8);
    const uint32_t a_csel = (uint32_t)(lane >> 4);
    const uint32_t aoff0 = a_row * STRIDE + a_csel * 16;
    const uint32_t aoff1 = (a_row + 16) * STRIDE + a_csel * 16;
    const uint32_t b_row  = (uint32_t)(wn * 32 + (lane & 7) + (lane >> 4) * 8);
    const uint32_t b_csel = (uint32_t)((lane >> 3) & 1);
    const uint32_t boff0 = b_row * STRIDE + b_csel * 16;
    const uint32_t boff1 = (b_row + 16) * STRIDE + b_csel * 16;

    // running sums (proper RN fp32 adds between chunks)
    float sum[2][4][4];
    #pragma unroll
    for (int i = 0; i < 2; ++i)
        #pragma unroll
        for (int j = 0; j < 4; ++j)
            #pragma unroll
            for (int r = 0; r < 4; ++r) sum[i][j][r] = 0.0f;

    float4 xv[4];
    {
        const float4* p = reinterpret_cast<const float4*>(Xrow);
        xv[0] = p[0]; xv[1] = p[1]; xv[2] = p[2]; xv[3] = p[3];
    }

    for (int t = 0; t < NCHUNK; ++t) {
        const int b = t & 1;

        // exact-split-store X(t) into the 3 planes of buffer b
        {
            uint4 u0[2], u1[2], u2[2];
            split3(xv[0].x, xv[0].y, u0[0].x, u1[0].x, u2[0].x);
            split3(xv[0].z, xv[0].w, u0[0].y, u1[0].y, u2[0].y);
            split3(xv[1].x, xv[1].y, u0[0].z, u1[0].z, u2[0].z);
            split3(xv[1].z, xv[1].w, u0[0].w, u1[0].w, u2[0].w);
            split3(xv[2].x, xv[2].y, u0[1].x, u1[1].x, u2[1].x);
            split3(xv[2].z, xv[2].w, u0[1].y, u1[1].y, u2[1].y);
            split3(xv[3].x, xv[3].y, u0[1].z, u1[1].z, u2[1].z);
            split3(xv[3].z, xv[3].w, u0[1].w, u1[1].w, u2[1].w);
            unsigned char* x0 = dsm + (3 * b + 0) * XSPLIT + xst;
            unsigned char* x1 = dsm + (3 * b + 1) * XSPLIT + xst;
            unsigned char* x2 = dsm + (3 * b + 2) * XSPLIT + xst;
            *reinterpret_cast<uint4*>(x0)      = u0[0];
            *reinterpret_cast<uint4*>(x0 + 16) = u0[1];
            *reinterpret_cast<uint4*>(x1)      = u1[0];
            *reinterpret_cast<uint4*>(x1 + 16) = u1[1];
            *reinterpret_cast<uint4*>(x2)      = u2[0];
            *reinterpret_cast<uint4*>(x2 + 16) = u2[1];
        }

        // prefetch X(t+1) into xv (xv dead after split-store; LDG in flight across wait+mma)
        if (t + 1 < NCHUNK) {
            const float4* p = reinterpret_cast<const float4*>(Xrow + (t + 1) * KC);
            xv[0] = p[0]; xv[1] = p[1]; xv[2] = p[2]; xv[3] = p[3];
        }

        if (t == NCHUNK - 1) { CPWAIT(0); } else { CPWAIT(1); }
        __syncthreads();

        // fresh accumulators per chunk (bounds tensor-core RZ accumulation bias)
        float acc[2][4][4];
        #pragma unroll
        for (int i = 0; i < 2; ++i)
            #pragma unroll
            for (int j = 0; j < 4; ++j)
                #pragma unroll
                for (int r = 0; r < 4; ++r) acc[i][j][r] = 0.0f;

        // consume buffer b
        const uint32_t xs = Bs + (uint32_t)(3 * b) * XSPLIT;
        const uint32_t ws = Bs + WOFF + (uint32_t)(3 * b) * WSPLIT;
        #pragma unroll
        for (int ks = 0; ks < 2; ++ks) {
            const uint32_t ko = (uint32_t)(ks * 32);
            uint32_t a[3][2][4], bx[3][8];
            #pragma unroll
            for (int s = 0; s < 3; ++s) {
                LDSM4(a[s][0], xs + s * XSPLIT + aoff0 + ko);
                LDSM4(a[s][1], xs + s * XSPLIT + aoff1 + ko);
                LDSM4(bx[s],     ws + s * WSPLIT + boff0 + ko);
                LDSM4(bx[s] + 4, ws + s * WSPLIT + boff1 + ko);
            }
            // products: (0,0) (0,1) (1,0) (1,1) (0,2) (2,0)
            #pragma unroll
            for (int nt = 0; nt < 4; ++nt) {
                MMA16816(acc[0][nt], a[0][0], bx[0][2 * nt], bx[0][2 * nt + 1]);
                MMA16816(acc[1][nt], a[0][1], bx[0][2 * nt], bx[0][2 * nt + 1]);
                MMA16816(acc[0][nt], a[0][0], bx[1][2 * nt], bx[1][2 * nt + 1]);
                MMA16816(acc[1][nt], a[0][1], bx[1][2 * nt], bx[1][2 * nt + 1]);
                MMA16816(acc[0][nt], a[1][0], bx[0][2 * nt], bx[0][2 * nt + 1]);
                MMA16816(acc[1][nt], a[1][1], bx[0][2 * nt], bx[0][2 * nt + 1]);
                MMA16816(acc[0][nt], a[1][0], bx[1][2 * nt], bx[1][2 * nt + 1]);
                MMA16816(acc[1][nt], a[1][1], bx[1][2 * nt], bx[1][2 * nt + 1]);
                MMA16816(acc[0][nt], a[0][0], bx[2][2 * nt], bx[2][2 * nt + 1]);
                MMA16816(acc[1][nt], a[0][1], bx[2][2 * nt], bx[2][2 * nt + 1]);
                MMA16816(acc[0][nt], a[2][0], bx[0][2 * nt], bx[0][2 * nt + 1]);
                MMA16816(acc[1][nt], a[2][1], bx[0][2 * nt], bx[0][2 * nt + 1]);
            }
        }

        // fold chunk result into running sum with RN adds
        #pragma unroll
        for (int i = 0; i < 2; ++i)
            #pragma unroll
            for (int j = 0; j < 4; ++j)
                #pragma unroll
                for (int r = 0; r < 4; ++r) sum[i][j][r] += acc[i][j][r];

        __syncthreads();

        // refill W buffer b with chunk t+2
        if (t + 2 < NCHUNK) {
            stage_w(Bs, t + 2, b, tid);
            CPCOMMIT();
        }
    }

    // ================= epilogue =================
    float (*Sc)[65] = reinterpret_cast<float(*)[65]>(dsm);
    float (*Fi)[8]  = reinterpret_cast<float(*)[8]>(dsm + TM * 65 * 4);

    #pragma unroll
    for (int mt = 0; mt < 2; ++mt)
        #pragma unroll
        for (int nt = 0; nt < 4; ++nt)
            #pragma unroll
            for (int r = 0; r < 4; ++r) {
                int row = wm * 32 + mt * 16 + (lane >> 2) + (r >> 1) * 8;
                int col = wn * 32 + nt * 8 + (lane & 3) * 2 + (r & 1);
                Sc[row][col] = sum[mt][nt][r] + s_bias[col];
            }
    __syncthreads();

    if (tid < TM) {
        unsigned long long taken = 0ULL;
        float vals[8];
        int idxs[8];
        #pragma unroll
        for (int k = 0; k < 8; ++k) {
            float bv = -3.4e38f;
            int bi = 0;
            for (int e = 0; e < NE; ++e) {
                float se = Sc[tid][e];
                bool avail = !((taken >> e) & 1ULL);
                if (avail && se > bv) { bv = se; bi = e; }
            }
            vals[k] = bv;
            idxs[k] = bi;
            taken |= 1ULL << bi;
        }
        float mx = fmaxf(vals[0], 0.0f);
        float denom = (float)(NE - 8) * __expf(-mx);
        #pragma unroll
        for (int k = 0; k < 8; ++k) denom += __expf(vals[k] - mx);
        float inv = 1.0f / denom;
        float z = __expf(-mx) * inv;
        for (int e = 0; e < NE; ++e) Sc[tid][e] = z;
        #pragma unroll
        for (int k = 0; k < 8; ++k) Sc[tid][idxs[k]] = __expf(vals[k] - mx) * inv;
        #pragma unroll
        for (int k = 0; k < 8; ++k) Fi[tid][k] = (float)idxs[k];
    }
    __syncthreads();

    float* ro = out + (size_t)tokbase * NE;
    for (int i = tid; i < TM * NE; i += NTHREADS) ro[i] = Sc[i >> 6][i & 63];
    float* io = out + (size_t)ntok * NE + (size_t)tokbase * 8;
    for (int i = tid; i < TM * 8; i += NTHREADS) io[i] = Fi[i >> 3][i & 7];
}

extern "C" void kernel_launch(void* const* d_in, const int* in_sizes, int n_in,
                              void* d_out, int out_size)
{
    const float* X = nullptr;
    const float* Wm = nullptr;
    const float* Bv = nullptr;
    int nx = 0;
    for (int i = 0; i < n_in; ++i) {
        if (in_sizes[i] == NE) Bv = (const float*)d_in[i];
        else if (in_sizes[i] == NE * KD) Wm = (const float*)d_in[i];
        else { X = (const float*)d_in[i]; nx = in_sizes[i]; }
    }
    int ntok = nx / KD;                 // 32768
    int grid = ntok / TM;               // 256

    cudaFuncSetAttribute(router_mma, cudaFuncAttributeMaxDynamicSharedMemorySize, DYN_SMEM);

    wconv_kernel<<<64, 256>>>(Wm);
    router_mma<<<grid, NTHREADS, DYN_SMEM>>>(X, Bv, (float*)d_out, ntok);
}

// round 14
// speedup vs baseline: 1.0023x; 1.0021x over previous
#include <cuda_runtime.h>
#include <cstdint>

#define NE 64
#define KD 2048
#define TM 128
#define KC 32                    // fp32 k-elements per chunk
#define NCHUNK (KD / KC)         // 64
#define NTHREADS 256
#define STRIDE 80                // smem row stride (bytes): gcd(5,8)=1 -> conflict-free ldmatrix

#define XSPLIT (TM * STRIDE)     // 10240 bytes: one X split plane
#define WOFF   (6 * XSPLIT)      // X double-buffer (2 bufs x 3 planes) = 61440
#define WSPLIT (NE * STRIDE)     // 5120 bytes: one W split plane
#define DYN_SMEM (WOFF + 6 * WSPLIT)   // 92160
// epilogue overlay: Sc[128][65] f32 + Fi[128][8] f32 = 37376 <= 92160

// pre-split W in final smem byte layout: [chunk][plane][64 rows x 80B]
__device__ __align__(16) unsigned char Wsc[NCHUNK][3][WSPLIT];

// ---------------- PTX helpers (base ISA only) ----------------
#define CPASYNC16(s, g) asm volatile("cp.async.cg.shared.global [%0], [%1], 16;" :: "r"(s), "l"(g))
#define CPCOMMIT()      asm volatile("cp.async.commit_group;")
#define CPWAIT(n)       asm volatile("cp.async.wait_group %0;" :: "n"(n))

#define LDSM4(r, addr) \
    asm volatile("ldmatrix.sync.aligned.m8n8.x4.shared.b16 {%0,%1,%2,%3}, [%4];" \
        : "=r"((r)[0]), "=r"((r)[1]), "=r"((r)[2]), "=r"((r)[3]) : "r"(addr))

#define MMA16816(d, a, b0, b1) \
    asm volatile("mma.sync.aligned.m16n8k16.row.col.f32.bf16.bf16.f32 " \
        "{%0,%1,%2,%3},{%4,%5,%6,%7},{%8,%9},{%0,%1,%2,%3};" \
        : "+f"((d)[0]), "+f"((d)[1]), "+f"((d)[2]), "+f"((d)[3]) \
        : "r"((a)[0]), "r"((a)[1]), "r"((a)[2]), "r"((a)[3]), "r"(b0), "r"(b1))

// exact 3-term split of an fp32 pair into bf16x2 planes (x = p0+p1+p2 to ~2^-33)
__device__ __forceinline__ void split3(float a, float b,
                                       uint32_t& p0, uint32_t& p1, uint32_t& p2)
{
    asm("cvt.rn.bf16x2.f32 %0, %1, %2;" : "=r"(p0) : "f"(b), "f"(a));
    float a1 = a - __uint_as_float(p0 << 16);
    float b1 = b - __uint_as_float(p0 & 0xffff0000u);
    asm("cvt.rn.bf16x2.f32 %0, %1, %2;" : "=r"(p1) : "f"(b1), "f"(a1));
    float a2 = a1 - __uint_as_float(p1 << 16);
    float b2 = b1 - __uint_as_float(p1 & 0xffff0000u);
    asm("cvt.rn.bf16x2.f32 %0, %1, %2;" : "=r"(p2) : "f"(b2), "f"(a2));
}

// ---------------- W pre-split kernel ----------------
__global__ void wconv_kernel(const float* __restrict__ W)
{
    int i = blockIdx.x * blockDim.x + threadIdx.x;  // 16384 threads, 8 f32 each
    int gi = i * 8;
    int e = gi >> 11;
    int k0 = gi & 2047;
    const float4* p = reinterpret_cast<const float4*>(W + (size_t)e * KD + k0);
    float4 v0 = p[0], v1 = p[1];
    uint4 u0, u1, u2;
    split3(v0.x, v0.y, u0.x, u1.x, u2.x);
    split3(v0.z, v0.w, u0.y, u1.y, u2.y);
    split3(v1.x, v1.y, u0.z, u1.z, u2.z);
    split3(v1.z, v1.w, u0.w, u1.w, u2.w);
    int c = k0 >> 5;
    uint32_t off = (uint32_t)(e * STRIDE + ((k0 & 31) >> 3) * 16);
    *reinterpret_cast<uint4*>(&Wsc[c][0][off]) = u0;
    *reinterpret_cast<uint4*>(&Wsc[c][1][off]) = u1;
    *reinterpret_cast<uint4*>(&Wsc[c][2][off]) = u2;
}

// ---------------- main kernel ----------------
extern __shared__ __align__(16) unsigned char dsm[];

__device__ __forceinline__ void stage_w(uint32_t Bs, int t, int buf, int tid)
{
    #pragma unroll
    for (int r = 0; r < 3; ++r) {
        int idx = tid + r * 256;          // 768 x 16B data chunks (3 planes x 64 rows x 4)
        int s = idx >> 8;                 // plane
        int row = (idx >> 2) & 63;
        int c = idx & 3;
        uint32_t off = (uint32_t)(row * STRIDE + c * 16);
        uint32_t dst = Bs + WOFF + (uint32_t)((3 * buf + s) * WSPLIT) + off;
        CPASYNC16(dst, &Wsc[t][s][0] + off);
    }
}

__global__ void __launch_bounds__(NTHREADS, 2)
router_mma(const float* __restrict__ X,
           const float* __restrict__ Bv,
           float* __restrict__ out, int ntok)
{
    __shared__ float s_bias[NE];

    const int tid = threadIdx.x;
    const int lane = tid & 31;
    const int wid = tid >> 5;
    const int wm = wid >> 1;           // token group (0..3) -> 32 tokens
    const int wn = wid & 1;            // expert group (0..1) -> 32 experts
    const int tokbase = blockIdx.x * TM;

    const uint32_t Bs = (uint32_t)__cvta_generic_to_shared(dsm);

    if (tid < NE) s_bias[tid] = Bv[tid];

    // prologue: stage W chunks 0,1
    stage_w(Bs, 0, 0, tid);
    CPCOMMIT();
    stage_w(Bs, 1, 1, tid);
    CPCOMMIT();

    // X staging mapping: thread -> (token, half-row of 16 f32)
    const int tok = tid >> 1, h = tid & 1;
    const float* Xrow = X + (size_t)(tokbase + tok) * KD + h * 16;
    const uint32_t xst = (uint32_t)(tok * STRIDE + h * 32);   // byte offset of this thread's 32B

    // ldmatrix lane offsets
    const uint32_t a_row  = (uint32_t)(wm * 32 + (lane & 7) + ((lane >> 3) & 1) * 8);
    const uint32_t a_csel = (uint32_t)(lane >> 4);
    const uint32_t aoff0 = a_row * STRIDE + a_csel * 16;
    const uint32_t aoff1 = (a_row + 16) * STRIDE + a_csel * 16;
    const uint32_t b_row  = (uint32_t)(wn * 32 + (lane & 7) + (lane >> 4) * 8);
    const uint32_t b_csel = (uint32_t)((lane >> 3) & 1);
    const uint32_t boff0 = b_row * STRIDE + b_csel * 16;
    const uint32_t boff1 = (b_row + 16) * STRIDE + b_csel * 16;

    // running sums (proper RN fp32 adds between chunks)
    float sum[2][4][4];
    #pragma unroll
    for (int i = 0; i < 2; ++i)
        #pragma unroll
        for (int j = 0; j < 4; ++j)
            #pragma unroll
            for (int r = 0; r < 4; ++r) sum[i][j][r] = 0.0f;

    float4 xv[4];
    {
        const float4* p = reinterpret_cast<const float4*>(Xrow);
        xv[0] = p[0]; xv[1] = p[1]; xv[2] = p[2]; xv[3] = p[3];
    }

    for (int t = 0; t < NCHUNK; ++t) {
        const int b = t & 1;

        // exact-split-store X(t) into the 3 planes of buffer b
        {
            uint4 u0[2], u1[2], u2[2];
            split3(xv[0].x, xv[0].y, u0[0].x, u1[0].x, u2[0].x);
            split3(xv[0].z, xv[0].w, u0[0].y, u1[0].y, u2[0].y);
            split3(xv[1].x, xv[1].y, u0[0].z, u1[0].z, u2[0].z);
            split3(xv[1].z, xv[1].w, u0[0].w, u1[0].w, u2[0].w);
            split3(xv[2].x, xv[2].y, u0[1].x, u1[1].x, u2[1].x);
            split3(xv[2].z, xv[2].w, u0[1].y, u1[1].y, u2[1].y);
            split3(xv[3].x, xv[3].y, u0[1].z, u1[1].z, u2[1].z);
            split3(xv[3].z, xv[3].w, u0[1].w, u1[1].w, u2[1].w);
            unsigned char* x0 = dsm + (3 * b + 0) * XSPLIT + xst;
            unsigned char* x1 = dsm + (3 * b + 1) * XSPLIT + xst;
            unsigned char* x2 = dsm + (3 * b + 2) * XSPLIT + xst;
            *reinterpret_cast<uint4*>(x0)      = u0[0];
            *reinterpret_cast<uint4*>(x0 + 16) = u0[1];
            *reinterpret_cast<uint4*>(x1)      = u1[0];
            *reinterpret_cast<uint4*>(x1 + 16) = u1[1];
            *reinterpret_cast<uint4*>(x2)      = u2[0];
            *reinterpret_cast<uint4*>(x2 + 16) = u2[1];
        }

        // prefetch X(t+1) into xv (xv dead after split-store; LDG in flight across wait+mma)
        if (t + 1 < NCHUNK) {
            const float4* p = reinterpret_cast<const float4*>(Xrow + (t + 1) * KC);
            xv[0] = p[0]; xv[1] = p[1]; xv[2] = p[2]; xv[3] = p[3];
        }

        if (t == NCHUNK - 1) { CPWAIT(0); } else { CPWAIT(1); }
        __syncthreads();

        // fresh accumulators per chunk (bounds tensor-core RZ accumulation bias)
        float acc[2][4][4];
        #pragma unroll
        for (int i = 0; i < 2; ++i)
            #pragma unroll
            for (int j = 0; j < 4; ++j)
                #pragma unroll
                for (int r = 0; r < 4; ++r) acc[i][j][r] = 0.0f;

        // consume buffer b
        const uint32_t xs = Bs + (uint32_t)(3 * b) * XSPLIT;
        const uint32_t ws = Bs + WOFF + (uint32_t)(3 * b) * WSPLIT;
        #pragma unroll
        for (int ks = 0; ks < 2; ++ks) {
            const uint32_t ko = (uint32_t)(ks * 32);
            uint32_t a[3][2][4], bx[3][8];
            #pragma unroll
            for (int s = 0; s < 3; ++s) {
                LDSM4(a[s][0], xs + s * XSPLIT + aoff0 + ko);
                LDSM4(a[s][1], xs + s * XSPLIT + aoff1 + ko);
                LDSM4(bx[s],     ws + s * WSPLIT + boff0 + ko);
                LDSM4(bx[s] + 4, ws + s * WSPLIT + boff1 + ko);
            }
            // products: (0,0) (0,1) (1,0) (1,1) (0,2) (2,0)
            #pragma unroll
            for (int nt = 0; nt < 4; ++nt) {
                MMA16816(acc[0][nt], a[0][0], bx[0][2 * nt], bx[0][2 * nt + 1]);
                MMA16816(acc[1][nt], a[0][1], bx[0][2 * nt], bx[0][2 * nt + 1]);
                MMA16816(acc[0][nt], a[0][0], bx[1][2 * nt], bx[1][2 * nt + 1]);
                MMA16816(acc[1][nt], a[0][1], bx[1][2 * nt], bx[1][2 * nt + 1]);
                MMA16816(acc[0][nt], a[1][0], bx[0][2 * nt], bx[0][2 * nt + 1]);
                MMA16816(acc[1][nt], a[1][1], bx[0][2 * nt], bx[0][2 * nt + 1]);
                MMA16816(acc[0][nt], a[1][0], bx[1][2 * nt], bx[1][2 * nt + 1]);
                MMA16816(acc[1][nt], a[1][1], bx[1][2 * nt], bx[1][2 * nt + 1]);
                MMA16816(acc[0][nt], a[0][0], bx[2][2 * nt], bx[2][2 * nt + 1]);
                MMA16816(acc[1][nt], a[0][1], bx[2][2 * nt], bx[2][2 * nt + 1]);
                MMA16816(acc[0][nt], a[2][0], bx[0][2 * nt], bx[0][2 * nt + 1]);
                MMA16816(acc[1][nt], a[2][1], bx[0][2 * nt], bx[0][2 * nt + 1]);
            }
        }

        // fold chunk result into running sum with RN adds
        #pragma unroll
        for (int i = 0; i < 2; ++i)
            #pragma unroll
            for (int j = 0; j < 4; ++j)
                #pragma unroll
                for (int r = 0; r < 4; ++r) sum[i][j][r] += acc[i][j][r];

        __syncthreads();

        // refill W buffer b with chunk t+2
        if (t + 2 < NCHUNK) {
            stage_w(Bs, t + 2, b, tid);
            CPCOMMIT();
        }
    }

    // ================= epilogue =================
    float (*Sc)[65] = reinterpret_cast<float(*)[65]>(dsm);
    float (*Fi)[8]  = reinterpret_cast<float(*)[8]>(dsm + TM * 65 * 4);

    #pragma unroll
    for (int mt = 0; mt < 2; ++mt)
        #pragma unroll
        for (int nt = 0; nt < 4; ++nt)
            #pragma unroll
            for (int r = 0; r < 4; ++r) {
                int row = wm * 32 + mt * 16 + (lane >> 2) + (r >> 1) * 8;
                int col = wn * 32 + nt * 8 + (lane & 3) * 2 + (r & 1);
                Sc[row][col] = sum[mt][nt][r] + s_bias[col];
            }
    __syncthreads();

    if (tid < TM) {
        unsigned long long taken = 0ULL;
        float vals[8];
        int idxs[8];
        #pragma unroll
        for (int k = 0; k < 8; ++k) {
            float bv = -3.4e38f;
            int bi = 0;
            for (int e = 0; e < NE; ++e) {
                float se = Sc[tid][e];
                bool avail = !((taken >> e) & 1ULL);
                if (avail && se > bv) { bv = se; bi = e; }
            }
            vals[k] = bv;
            idxs[k] = bi;
            taken |= 1ULL << bi;
        }
        float mx = fmaxf(vals[0], 0.0f);
        float denom = (float)(NE - 8) * __expf(-mx);
        #pragma unroll
        for (int k = 0; k < 8; ++k) denom += __expf(vals[k] - mx);
        float inv = 1.0f / denom;
        float z = __expf(-mx) * inv;
        for (int e = 0; e < NE; ++e) Sc[tid][e] = z;
        #pragma unroll
        for (int k = 0; k < 8; ++k) Sc[tid][idxs[k]] = __expf(vals[k] - mx) * inv;
        #pragma unroll
        for (int k = 0; k < 8; ++k) Fi[tid][k] = (float)idxs[k];
    }
    __syncthreads();

    float* ro = out + (size_t)tokbase * NE;
    for (int i = tid; i < TM * NE; i += NTHREADS) ro[i] = Sc[i >> 6][i & 63];
    float* io = out + (size_t)ntok * NE + (size_t)tokbase * 8;
    for (int i = tid; i < TM * 8; i += NTHREADS) io[i] = Fi[i >> 3][i & 7];
}

extern "C" void kernel_launch(void* const* d_in, const int* in_sizes, int n_in,
                              void* d_out, int out_size)
{
    const float* X = nullptr;
    const float* Wm = nullptr;
    const float* Bv = nullptr;
    int nx = 0;
    for (int i = 0; i < n_in; ++i) {
        if (in_sizes[i] == NE) Bv = (const float*)d_in[i];
        else if (in_sizes[i] == NE * KD) Wm = (const float*)d_in[i];
        else { X = (const float*)d_in[i]; nx = in_sizes[i]; }
    }
    int ntok = nx / KD;                 // 32768
    int grid = ntok / TM;               // 256

    cudaFuncSetAttribute(router_mma, cudaFuncAttributeMaxDynamicSharedMemorySize, DYN_SMEM);

    wconv_kernel<<<64, 256>>>(Wm);
    router_mma<<<grid, NTHREADS, DYN_SMEM>>>(X, Bv, (float*)d_out, ntok);
}

// round 15
// speedup vs baseline: 1.5282x; 1.5246x over previous
#include <cuda_runtime.h>
#include <cuda_fp16.h>
#include <cstdint>

#define NE 64
#define KD 2048
#define TM 128
#define KC 32                    // fp32 k-elements per chunk
#define NCHUNK (KD / KC)         // 64
#define NTHREADS 256
#define STRIDE 80                // smem row stride (bytes): gcd(5,8)=1 -> conflict-free ldmatrix

#define XSPLIT (TM * STRIDE)     // 10240 bytes: one X split plane (128 rows x 64B data)
#define WOFF   (4 * XSPLIT)      // X double-buffer (2 bufs x 2 planes) = 40960
#define WSPLIT (NE * STRIDE)     // 5120 bytes: one W split plane
#define DYN_SMEM (WOFF + 6 * WSPLIT)   // + W triple-buffer (3 bufs x 2 planes) = 71680
// epilogue overlay: Sc[128][65] f32 + Fi[128][8] f32 = 37376 <= 71680

#define WSCALE 64.0f
#define WINV   0.015625f         // 1/64

// pre-split 64*W (fp16 2-plane) in final smem byte layout: [chunk][plane][64 rows x 80B]
__device__ __align__(16) unsigned char Wsc[NCHUNK][2][WSPLIT];

// ---------------- PTX helpers (base ISA only) ----------------
#define CPASYNC16(s, g) asm volatile("cp.async.cg.shared.global [%0], [%1], 16;" :: "r"(s), "l"(g))
#define CPCOMMIT()      asm volatile("cp.async.commit_group;")
#define CPWAIT(n)       asm volatile("cp.async.wait_group %0;" :: "n"(n))

#define LDSM4(r, addr) \
    asm volatile("ldmatrix.sync.aligned.m8n8.x4.shared.b16 {%0,%1,%2,%3}, [%4];" \
        : "=r"((r)[0]), "=r"((r)[1]), "=r"((r)[2]), "=r"((r)[3]) : "r"(addr))

#define MMA16816(d, a, b0, b1) \
    asm volatile("mma.sync.aligned.m16n8k16.row.col.f32.f16.f16.f32 " \
        "{%0,%1,%2,%3},{%4,%5,%6,%7},{%8,%9},{%0,%1,%2,%3};" \
        : "+f"((d)[0]), "+f"((d)[1]), "+f"((d)[2]), "+f"((d)[3]) \
        : "r"((a)[0]), "r"((a)[1]), "r"((a)[2]), "r"((a)[3]), "r"(b0), "r"(b1))

// 2-term fp16 split of an fp32 pair (x = h0 + h1 + eps, eps ~ 2^-23|x|)
// lower-k element in low 16 bits
__device__ __forceinline__ void split2h(float a, float b, uint32_t& p0, uint32_t& p1)
{
    __half2 h = __float22half2_rn(make_float2(a, b));
    float2 r = __half22float2(h);
    __half2 l = __float22half2_rn(make_float2(a - r.x, b - r.y));
    p0 = *reinterpret_cast<uint32_t*>(&h);
    p1 = *reinterpret_cast<uint32_t*>(&l);
}

// ---------------- W pre-split kernel (scales by 64) ----------------
__global__ void wconv_kernel(const float* __restrict__ W)
{
    int i = blockIdx.x * blockDim.x + threadIdx.x;  // 16384 threads, 8 f32 each
    int gi = i * 8;
    int e = gi >> 11;
    int k0 = gi & 2047;
    const float4* p = reinterpret_cast<const float4*>(W + (size_t)e * KD + k0);
    float4 v0 = p[0], v1 = p[1];
    uint4 u0, u1;
    split2h(v0.x * WSCALE, v0.y * WSCALE, u0.x, u1.x);
    split2h(v0.z * WSCALE, v0.w * WSCALE, u0.y, u1.y);
    split2h(v1.x * WSCALE, v1.y * WSCALE, u0.z, u1.z);
    split2h(v1.z * WSCALE, v1.w * WSCALE, u0.w, u1.w);
    int c = k0 >> 5;
    uint32_t off = (uint32_t)(e * STRIDE + ((k0 & 31) >> 3) * 16);
    *reinterpret_cast<uint4*>(&Wsc[c][0][off]) = u0;
    *reinterpret_cast<uint4*>(&Wsc[c][1][off]) = u1;
}

// ---------------- main kernel ----------------
extern __shared__ __align__(16) unsigned char dsm[];

__device__ __forceinline__ void stage_w(uint32_t Bs, int t, int buf, int tid)
{
    #pragma unroll
    for (int r = 0; r < 2; ++r) {
        int idx = tid + r * 256;          // 512 x 16B data chunks (2 planes x 64 rows x 4)
        int s = idx >> 8;                 // plane
        int row = (idx >> 2) & 63;
        int c = idx & 3;
        uint32_t off = (uint32_t)(row * STRIDE + c * 16);
        uint32_t dst = Bs + WOFF + (uint32_t)((2 * buf + s) * WSPLIT) + off;
        CPASYNC16(dst, &Wsc[t][s][0] + off);
    }
}

__global__ void __launch_bounds__(NTHREADS, 2)
router_mma(const float* __restrict__ X,
           const float* __restrict__ Bv,
           float* __restrict__ out, int ntok)
{
    __shared__ float s_bias[NE];

    const int tid = threadIdx.x;
    const int lane = tid & 31;
    const int wid = tid >> 5;
    const int wm = wid >> 1;           // token group (0..3) -> 32 tokens
    const int wn = wid & 1;            // expert group (0..1) -> 32 experts
    const int tokbase = blockIdx.x * TM;

    const uint32_t Bs = (uint32_t)__cvta_generic_to_shared(dsm);

    if (tid < NE) s_bias[tid] = Bv[tid];

    // prologue: stage W chunks 0,1 into W bufs 0,1
    stage_w(Bs, 0, 0, tid);
    CPCOMMIT();
    stage_w(Bs, 1, 1, tid);
    CPCOMMIT();

    // X staging mapping: thread -> (token, half-row of 16 f32)
    const int tok = tid >> 1, h = tid & 1;
    const float* Xrow = X + (size_t)(tokbase + tok) * KD + h * 16;
    const uint32_t xst = (uint32_t)(tok * STRIDE + h * 32);   // byte offset of this thread's 32B

    // ldmatrix lane offsets
    const uint32_t a_row  = (uint32_t)(wm * 32 + (lane & 7) + ((lane >> 3) & 1) * 8);
    const uint32_t a_csel = (uint32_t)(lane >> 4);
    const uint32_t aoff0 = a_row * STRIDE + a_csel * 16;
    const uint32_t aoff1 = (a_row + 16) * STRIDE + a_csel * 16;
    const uint32_t b_row  = (uint32_t)(wn * 32 + (lane & 7) + (lane >> 4) * 8);
    const uint32_t b_csel = (uint32_t)((lane >> 3) & 1);
    const uint32_t boff0 = b_row * STRIDE + b_csel * 16;
    const uint32_t boff1 = (b_row + 16) * STRIDE + b_csel * 16;

    // running sums (proper RN fp32 adds between chunks)
    float sum[2][4][4];
    #pragma unroll
    for (int i = 0; i < 2; ++i)
        #pragma unroll
        for (int j = 0; j < 4; ++j)
            #pragma unroll
            for (int r = 0; r < 4; ++r) sum[i][j][r] = 0.0f;

    float4 xv[4];
    {
        const float4* p = reinterpret_cast<const float4*>(Xrow);
        xv[0] = p[0]; xv[1] = p[1]; xv[2] = p[2]; xv[3] = p[3];
    }

    for (int t = 0; t < NCHUNK; ++t) {
        const int xb = t & 1;
        const int wb = t % 3;

        // fp16-split-store X(t) into the 2 planes of X buffer xb
        {
            uint4 u0[2], u1[2];
            split2h(xv[0].x, xv[0].y, u0[0].x, u1[0].x);
            split2h(xv[0].z, xv[0].w, u0[0].y, u1[0].y);
            split2h(xv[1].x, xv[1].y, u0[0].z, u1[0].z);
            split2h(xv[1].z, xv[1].w, u0[0].w, u1[0].w);
            split2h(xv[2].x, xv[2].y, u0[1].x, u1[1].x);
            split2h(xv[2].z, xv[2].w, u0[1].y, u1[1].y);
            split2h(xv[3].x, xv[3].y, u0[1].z, u1[1].z);
            split2h(xv[3].z, xv[3].w, u0[1].w, u1[1].w);
            unsigned char* x0 = dsm + (2 * xb + 0) * XSPLIT + xst;
            unsigned char* x1 = dsm + (2 * xb + 1) * XSPLIT + xst;
            *reinterpret_cast<uint4*>(x0)      = u0[0];
            *reinterpret_cast<uint4*>(x0 + 16) = u0[1];
            *reinterpret_cast<uint4*>(x1)      = u1[0];
            *reinterpret_cast<uint4*>(x1 + 16) = u1[1];
        }

        // prefetch X(t+1) into xv (xv dead after split-store)
        if (t + 1 < NCHUNK) {
            const float4* p = reinterpret_cast<const float4*>(Xrow + (t + 1) * KC);
            xv[0] = p[0]; xv[1] = p[1]; xv[2] = p[2]; xv[3] = p[3];
        }

        // W chunk t's cp.async group must be complete (newest pending = chunk t+1's group)
        if (t + 1 < NCHUNK) { CPWAIT(1); } else { CPWAIT(0); }
        __syncthreads();   // single barrier per chunk

        // refill W buffer (t+2)%3 with chunk t+2 (safe: last read of that buf was
        // chunk t-1 at iter t-1, completed before this barrier)
        if (t + 2 < NCHUNK) {
            stage_w(Bs, t + 2, (t + 2) % 3, tid);
            CPCOMMIT();
        }

        // fresh accumulators per chunk (bounds tensor-core RZ accumulation bias)
        float acc[2][4][4];
        #pragma unroll
        for (int i = 0; i < 2; ++i)
            #pragma unroll
            for (int j = 0; j < 4; ++j)
                #pragma unroll
                for (int r = 0; r < 4; ++r) acc[i][j][r] = 0.0f;

        // consume X buf xb, W buf wb
        const uint32_t xs = Bs + (uint32_t)(2 * xb) * XSPLIT;
        const uint32_t ws = Bs + WOFF + (uint32_t)(2 * wb) * WSPLIT;
        #pragma unroll
        for (int ks = 0; ks < 2; ++ks) {
            const uint32_t ko = (uint32_t)(ks * 32);
            uint32_t a[2][2][4], bx[2][8];
            #pragma unroll
            for (int s = 0; s < 2; ++s) {
                LDSM4(a[s][0], xs + s * XSPLIT + aoff0 + ko);
                LDSM4(a[s][1], xs + s * XSPLIT + aoff1 + ko);
                LDSM4(bx[s],     ws + s * WSPLIT + boff0 + ko);
                LDSM4(bx[s] + 4, ws + s * WSPLIT + boff1 + ko);
            }
            // products: (h0,g0) (h0,g1) (h1,g0)   [dropped (h1,g1) ~ 2^-22]
            #pragma unroll
            for (int nt = 0; nt < 4; ++nt) {
                MMA16816(acc[0][nt], a[0][0], bx[0][2 * nt], bx[0][2 * nt + 1]);
                MMA16816(acc[1][nt], a[0][1], bx[0][2 * nt], bx[0][2 * nt + 1]);
                MMA16816(acc[0][nt], a[0][0], bx[1][2 * nt], bx[1][2 * nt + 1]);
                MMA16816(acc[1][nt], a[0][1], bx[1][2 * nt], bx[1][2 * nt + 1]);
                MMA16816(acc[0][nt], a[1][0], bx[0][2 * nt], bx[0][2 * nt + 1]);
                MMA16816(acc[1][nt], a[1][1], bx[0][2 * nt], bx[0][2 * nt + 1]);
            }
        }

        // fold chunk result into running sum with RN adds
        #pragma unroll
        for (int i = 0; i < 2; ++i)
            #pragma unroll
            for (int j = 0; j < 4; ++j)
                #pragma unroll
                for (int r = 0; r < 4; ++r) sum[i][j][r] += acc[i][j][r];
    }

    __syncthreads();

    // ================= epilogue =================
    float (*Sc)[65] = reinterpret_cast<float(*)[65]>(dsm);
    float (*Fi)[8]  = reinterpret_cast<float(*)[8]>(dsm + TM * 65 * 4);

    #pragma unroll
    for (int mt = 0; mt < 2; ++mt)
        #pragma unroll
        for (int nt = 0; nt < 4; ++nt)
            #pragma unroll
            for (int r = 0; r < 4; ++r) {
                int row = wm * 32 + mt * 16 + (lane >> 2) + (r >> 1) * 8;
                int col = wn * 32 + nt * 8 + (lane & 3) * 2 + (r & 1);
                Sc[row][col] = sum[mt][nt][r] * WINV + s_bias[col];
            }
    __syncthreads();

    if (tid < TM) {
        unsigned long long taken = 0ULL;
        float vals[8];
        int idxs[8];
        #pragma unroll
        for (int k = 0; k < 8; ++k) {
            float bv = -3.4e38f;
            int bi = 0;
            for (int e = 0; e < NE; ++e) {
                float se = Sc[tid][e];
                bool avail = !((taken >> e) & 1ULL);
                if (avail && se > bv) { bv = se; bi = e; }
            }
            vals[k] = bv;
            idxs[k] = bi;
            taken |= 1ULL << bi;
        }
        float mx = fmaxf(vals[0], 0.0f);
        float denom = (float)(NE - 8) * __expf(-mx);
        #pragma unroll
        for (int k = 0; k < 8; ++k) denom += __expf(vals[k] - mx);
        float inv = 1.0f / denom;
        float z = __expf(-mx) * inv;
        for (int e = 0; e < NE; ++e) Sc[tid][e] = z;
        #pragma unroll
        for (int k = 0; k < 8; ++k) Sc[tid][idxs[k]] = __expf(vals[k] - mx) * inv;
        #pragma unroll
        for (int k = 0; k < 8; ++k) Fi[tid][k] = (float)idxs[k];
    }
    __syncthreads();

    float* ro = out + (size_t)tokbase * NE;
    for (int i = tid; i < TM * NE; i += NTHREADS) ro[i] = Sc[i >> 6][i & 63];
    float* io = out + (size_t)ntok * NE + (size_t)tokbase * 8;
    for (int i = tid; i < TM * 8; i += NTHREADS) io[i] = Fi[i >> 3][i & 7];
}

extern "C" void kernel_launch(void* const* d_in, const int* in_sizes, int n_in,
                              void* d_out, int out_size)
{
    const float* X = nullptr;
    const float* Wm = nullptr;
    const float* Bv = nullptr;
    int nx = 0;
    for (int i = 0; i < n_in; ++i) {
        if (in_sizes[i] == NE) Bv = (const float*)d_in[i];
        else if (in_sizes[i] == NE * KD) Wm = (const float*)d_in[i];
        else { X = (const float*)d_in[i]; nx = in_sizes[i]; }
    }
    int ntok = nx / KD;                 // 32768
    int grid = ntok / TM;               // 256

    cudaFuncSetAttribute(router_mma, cudaFuncAttributeMaxDynamicSharedMemorySize, DYN_SMEM);

    wconv_kernel<<<64, 256>>>(Wm);
    router_mma<<<grid, NTHREADS, DYN_SMEM>>>(X, Bv, (float*)d_out, ntok);
}

// round 16
// speedup vs baseline: 1.5286x; 1.0003x over previous
#include <cuda_runtime.h>
#include <cuda_fp16.h>
#include <cstdint>

#define NE 64
#define KD 2048
#define TM 128
#define KC 32                    // fp32 k-elements per chunk
#define NCHUNK (KD / KC)         // 64
#define NTHREADS 256
#define STRIDE 80                // smem row stride (bytes): gcd(5,8)=1 -> conflict-free ldmatrix

#define XSPLIT (TM * STRIDE)     // 10240 bytes: one X split plane (128 rows x 64B data)
#define WOFF   (4 * XSPLIT)      // X double-buffer (2 bufs x 2 planes) = 40960
#define WSPLIT (NE * STRIDE)     // 5120 bytes: one W split plane
#define DYN_SMEM (WOFF + 6 * WSPLIT)   // + W triple-buffer (3 bufs x 2 planes) = 71680
// epilogue overlay: Sc[128][65] f32 + Fi[128][8] f32 = 37376 <= 71680

#define WSCALE 64.0f
#define WINV   0.015625f         // 1/64

// pre-split 64*W (fp16 2-plane) in final smem byte layout: [chunk][plane][64 rows x 80B]
__device__ __align__(16) unsigned char Wsc[NCHUNK][2][WSPLIT];

// ---------------- PTX helpers (base ISA only) ----------------
#define CPASYNC16(s, g) asm volatile("cp.async.cg.shared.global [%0], [%1], 16;" :: "r"(s), "l"(g))
#define CPCOMMIT()      asm volatile("cp.async.commit_group;")
#define CPWAIT(n)       asm volatile("cp.async.wait_group %0;" :: "n"(n))

#define LDSM4(r, addr) \
    asm volatile("ldmatrix.sync.aligned.m8n8.x4.shared.b16 {%0,%1,%2,%3}, [%4];" \
        : "=r"((r)[0]), "=r"((r)[1]), "=r"((r)[2]), "=r"((r)[3]) : "r"(addr))

#define MMA16816(d, a, b0, b1) \
    asm volatile("mma.sync.aligned.m16n8k16.row.col.f32.f16.f16.f32 " \
        "{%0,%1,%2,%3},{%4,%5,%6,%7},{%8,%9},{%0,%1,%2,%3};" \
        : "+f"((d)[0]), "+f"((d)[1]), "+f"((d)[2]), "+f"((d)[3]) \
        : "r"((a)[0]), "r"((a)[1]), "r"((a)[2]), "r"((a)[3]), "r"(b0), "r"(b1))

// 2-term fp16 split of an fp32 pair (x = h0 + h1 + eps, eps ~ 2^-23|x|)
// lower-k element in low 16 bits
__device__ __forceinline__ void split2h(float a, float b, uint32_t& p0, uint32_t& p1)
{
    __half2 h = __float22half2_rn(make_float2(a, b));
    float2 r = __half22float2(h);
    __half2 l = __float22half2_rn(make_float2(a - r.x, b - r.y));
    p0 = *reinterpret_cast<uint32_t*>(&h);
    p1 = *reinterpret_cast<uint32_t*>(&l);
}

// ---------------- W pre-split kernel (scales by 64) ----------------
__global__ void wconv_kernel(const float* __restrict__ W)
{
    int i = blockIdx.x * blockDim.x + threadIdx.x;  // 16384 threads, 8 f32 each
    int gi = i * 8;
    int e = gi >> 11;
    int k0 = gi & 2047;
    const float4* p = reinterpret_cast<const float4*>(W + (size_t)e * KD + k0);
    float4 v0 = p[0], v1 = p[1];
    uint4 u0, u1;
    split2h(v0.x * WSCALE, v0.y * WSCALE, u0.x, u1.x);
    split2h(v0.z * WSCALE, v0.w * WSCALE, u0.y, u1.y);
    split2h(v1.x * WSCALE, v1.y * WSCALE, u0.z, u1.z);
    split2h(v1.z * WSCALE, v1.w * WSCALE, u0.w, u1.w);
    int c = k0 >> 5;
    uint32_t off = (uint32_t)(e * STRIDE + ((k0 & 31) >> 3) * 16);
    *reinterpret_cast<uint4*>(&Wsc[c][0][off]) = u0;
    *reinterpret_cast<uint4*>(&Wsc[c][1][off]) = u1;
}

// ---------------- main kernel ----------------
extern __shared__ __align__(16) unsigned char dsm[];

__device__ __forceinline__ void stage_w(uint32_t Bs, int t, int buf, int tid)
{
    #pragma unroll
    for (int r = 0; r < 2; ++r) {
        int idx = tid + r * 256;          // 512 x 16B data chunks (2 planes x 64 rows x 4)
        int s = idx >> 8;                 // plane
        int row = (idx >> 2) & 63;
        int c = idx & 3;
        uint32_t off = (uint32_t)(row * STRIDE + c * 16);
        uint32_t dst = Bs + WOFF + (uint32_t)((2 * buf + s) * WSPLIT) + off;
        CPASYNC16(dst, &Wsc[t][s][0] + off);
    }
}

__global__ void __launch_bounds__(NTHREADS, 2)
router_mma(const float* __restrict__ X,
           const float* __restrict__ Bv,
           float* __restrict__ out, int ntok)
{
    __shared__ float s_bias[NE];

    const int tid = threadIdx.x;
    const int lane = tid & 31;
    const int wid = tid >> 5;
    const int wm = wid >> 1;           // token group (0..3) -> 32 tokens
    const int wn = wid & 1;            // expert group (0..1) -> 32 experts
    const int tokbase = blockIdx.x * TM;

    const uint32_t Bs = (uint32_t)__cvta_generic_to_shared(dsm);

    if (tid < NE) s_bias[tid] = Bv[tid];

    // prologue: stage W chunks 0,1 into W bufs 0,1
    stage_w(Bs, 0, 0, tid);
    CPCOMMIT();
    stage_w(Bs, 1, 1, tid);
    CPCOMMIT();

    // X staging mapping: thread -> (token, half-row of 16 f32)
    const int tok = tid >> 1, h = tid & 1;
    const float* Xrow = X + (size_t)(tokbase + tok) * KD + h * 16;
    const uint32_t xst = (uint32_t)(tok * STRIDE + h * 32);   // byte offset of this thread's 32B

    // ldmatrix lane offsets
    const uint32_t a_row  = (uint32_t)(wm * 32 + (lane & 7) + ((lane >> 3) & 1) * 8);
    const uint32_t a_csel = (uint32_t)(lane >> 4);
    const uint32_t aoff0 = a_row * STRIDE + a_csel * 16;
    const uint32_t aoff1 = (a_row + 16) * STRIDE + a_csel * 16;
    const uint32_t b_row  = (uint32_t)(wn * 32 + (lane & 7) + (lane >> 4) * 8);
    const uint32_t b_csel = (uint32_t)((lane >> 3) & 1);
    const uint32_t boff0 = b_row * STRIDE + b_csel * 16;
    const uint32_t boff1 = (b_row + 16) * STRIDE + b_csel * 16;

    // running sums (proper RN fp32 adds between chunks)
    float sum[2][4][4];
    #pragma unroll
    for (int i = 0; i < 2; ++i)
        #pragma unroll
        for (int j = 0; j < 4; ++j)
            #pragma unroll
            for (int r = 0; r < 4; ++r) sum[i][j][r] = 0.0f;

    float4 xv[4];
    {
        const float4* p = reinterpret_cast<const float4*>(Xrow);
        xv[0] = p[0]; xv[1] = p[1]; xv[2] = p[2]; xv[3] = p[3];
    }

    for (int t = 0; t < NCHUNK; ++t) {
        const int xb = t & 1;
        const int wb = t % 3;

        // fp16-split-store X(t) into the 2 planes of X buffer xb
        {
            uint4 u0[2], u1[2];
            split2h(xv[0].x, xv[0].y, u0[0].x, u1[0].x);
            split2h(xv[0].z, xv[0].w, u0[0].y, u1[0].y);
            split2h(xv[1].x, xv[1].y, u0[0].z, u1[0].z);
            split2h(xv[1].z, xv[1].w, u0[0].w, u1[0].w);
            split2h(xv[2].x, xv[2].y, u0[1].x, u1[1].x);
            split2h(xv[2].z, xv[2].w, u0[1].y, u1[1].y);
            split2h(xv[3].x, xv[3].y, u0[1].z, u1[1].z);
            split2h(xv[3].z, xv[3].w, u0[1].w, u1[1].w);
            unsigned char* x0 = dsm + (2 * xb + 0) * XSPLIT + xst;
            unsigned char* x1 = dsm + (2 * xb + 1) * XSPLIT + xst;
            *reinterpret_cast<uint4*>(x0)      = u0[0];
            *reinterpret_cast<uint4*>(x0 + 16) = u0[1];
            *reinterpret_cast<uint4*>(x1)      = u1[0];
            *reinterpret_cast<uint4*>(x1 + 16) = u1[1];
        }

        // prefetch X(t+1) into xv (xv dead after split-store)
        if (t + 1 < NCHUNK) {
            const float4* p = reinterpret_cast<const float4*>(Xrow + (t + 1) * KC);
            xv[0] = p[0]; xv[1] = p[1]; xv[2] = p[2]; xv[3] = p[3];
        }

        // W chunk t's cp.async group must be complete (newest pending = chunk t+1's group)
        if (t + 1 < NCHUNK) { CPWAIT(1); } else { CPWAIT(0); }
        __syncthreads();   // single barrier per chunk

        // refill W buffer (t+2)%3 with chunk t+2 (safe: last read of that buf was
        // chunk t-1 at iter t-1, completed before this barrier)
        if (t + 2 < NCHUNK) {
            stage_w(Bs, t + 2, (t + 2) % 3, tid);
            CPCOMMIT();
        }

        // fresh accumulators per chunk (bounds tensor-core RZ accumulation bias)
        float acc[2][4][4];
        #pragma unroll
        for (int i = 0; i < 2; ++i)
            #pragma unroll
            for (int j = 0; j < 4; ++j)
                #pragma unroll
                for (int r = 0; r < 4; ++r) acc[i][j][r] = 0.0f;

        // consume X buf xb, W buf wb
        const uint32_t xs = Bs + (uint32_t)(2 * xb) * XSPLIT;
        const uint32_t ws = Bs + WOFF + (uint32_t)(2 * wb) * WSPLIT;
        #pragma unroll
        for (int ks = 0; ks < 2; ++ks) {
            const uint32_t ko = (uint32_t)(ks * 32);
            uint32_t a[2][2][4], bx[2][8];
            #pragma unroll
            for (int s = 0; s < 2; ++s) {
                LDSM4(a[s][0], xs + s * XSPLIT + aoff0 + ko);
                LDSM4(a[s][1], xs + s * XSPLIT + aoff1 + ko);
                LDSM4(bx[s],     ws + s * WSPLIT + boff0 + ko);
                LDSM4(bx[s] + 4, ws + s * WSPLIT + boff1 + ko);
            }
            // products: (h0,g0) (h0,g1) (h1,g0)   [dropped (h1,g1) ~ 2^-22]
            #pragma unroll
            for (int nt = 0; nt < 4; ++nt) {
                MMA16816(acc[0][nt], a[0][0], bx[0][2 * nt], bx[0][2 * nt + 1]);
                MMA16816(acc[1][nt], a[0][1], bx[0][2 * nt], bx[0][2 * nt + 1]);
                MMA16816(acc[0][nt], a[0][0], bx[1][2 * nt], bx[1][2 * nt + 1]);
                MMA16816(acc[1][nt], a[0][1], bx[1][2 * nt], bx[1][2 * nt + 1]);
                MMA16816(acc[0][nt], a[1][0], bx[0][2 * nt], bx[0][2 * nt + 1]);
                MMA16816(acc[1][nt], a[1][1], bx[0][2 * nt], bx[0][2 * nt + 1]);
            }
        }

        // fold chunk result into running sum with RN adds
        #pragma unroll
        for (int i = 0; i < 2; ++i)
            #pragma unroll
            for (int j = 0; j < 4; ++j)
                #pragma unroll
                for (int r = 0; r < 4; ++r) sum[i][j][r] += acc[i][j][r];
    }

    __syncthreads();

    // ================= epilogue =================
    float (*Sc)[65] = reinterpret_cast<float(*)[65]>(dsm);
    float (*Fi)[8]  = reinterpret_cast<float(*)[8]>(dsm + TM * 65 * 4);

    #pragma unroll
    for (int mt = 0; mt < 2; ++mt)
        #pragma unroll
        for (int nt = 0; nt < 4; ++nt)
            #pragma unroll
            for (int r = 0; r < 4; ++r) {
                int row = wm * 32 + mt * 16 + (lane >> 2) + (r >> 1) * 8;
                int col = wn * 32 + nt * 8 + (lane & 3) * 2 + (r & 1);
                Sc[row][col] = sum[mt][nt][r] * WINV + s_bias[col];
            }
    __syncthreads();

    if (tid < TM) {
        unsigned long long taken = 0ULL;
        float vals[8];
        int idxs[8];
        #pragma unroll
        for (int k = 0; k < 8; ++k) {
            float bv = -3.4e38f;
            int bi = 0;
            for (int e = 0; e < NE; ++e) {
                float se = Sc[tid][e];
                bool avail = !((taken >> e) & 1ULL);
                if (avail && se > bv) { bv = se; bi = e; }
            }
            vals[k] = bv;
            idxs[k] = bi;
            taken |= 1ULL << bi;
        }
        float mx = fmaxf(vals[0], 0.0f);
        float denom = (float)(NE - 8) * __expf(-mx);
        #pragma unroll
        for (int k = 0; k < 8; ++k) denom += __expf(vals[k] - mx);
        float inv = 1.0f / denom;
        float z = __expf(-mx) * inv;
        for (int e = 0; e < NE; ++e) Sc[tid][e] = z;
        #pragma unroll
        for (int k = 0; k < 8; ++k) Sc[tid][idxs[k]] = __expf(vals[k] - mx) * inv;
        #pragma unroll
        for (int k = 0; k < 8; ++k) Fi[tid][k] = (float)idxs[k];
    }
    __syncthreads();

    float* ro = out + (size_t)tokbase * NE;
    for (int i = tid; i < TM * NE; i += NTHREADS) ro[i] = Sc[i >> 6][i & 63];
    float* io = out + (size_t)ntok * NE + (size_t)tokbase * 8;
    for (int i = tid; i < TM * 8; i += NTHREADS) io[i] = Fi[i >> 3][i & 7];
}

extern "C" void kernel_launch(void* const* d_in, const int* in_sizes, int n_in,
                              void* d_out, int out_size)
{
    const float* X = nullptr;
    const float* Wm = nullptr;
    const float* Bv = nullptr;
    int nx = 0;
    for (int i = 0; i < n_in; ++i) {
        if (in_sizes[i] == NE) Bv = (const float*)d_in[i];
        else if (in_sizes[i] == NE * KD) Wm = (const float*)d_in[i];
        else { X = (const float*)d_in[i]; nx = in_sizes[i]; }
    }
    int ntok = nx / KD;                 // 32768
    int grid = ntok / TM;               // 256

    cudaFuncSetAttribute(router_mma, cudaFuncAttributeMaxDynamicSharedMemorySize, DYN_SMEM);

    wconv_kernel<<<64, 256>>>(Wm);
    router_mma<<<grid, NTHREADS, DYN_SMEM>>>(X, Bv, (float*)d_out, ntok);
}